// round 17
// baseline (speedup 1.0000x reference)
#include <cuda_runtime.h>
#include <math_constants.h>

#define BB 4
#define HH 512
#define WW 512
#define HW (HH*WW)
#define NKPT 512
#define CAP 65536
#define NFEAT 128

#define TILE 64
#define HALO 15
#define LDIM (TILE + 2*HALO)     // 94
#define GR 3                     // guard rows (top/bottom)
#define GC 4                     // guard cols left (16B alignment)
#define RROWS (LDIM + 2*GR)      // 100
#define SPITCH 104
#define BUF (RROWS*SPITCH)       // 10400
#define WPR 5                    // bit-words per row (slots 0,4 = zero guards)
#define NMS_SMEM (BUF*4*2 + RROWS*WPR*4*2)
#define NMS_THREADS 1024
#define NMS_NW (NMS_THREADS/32)

#define SURVCAP 3072

// Output layout (float32, reference tuple order)
#define OFF_SCORE 0
#define OFF_KPTS  (BB*HW)
#define OFF_FEAS  (OFF_KPTS + BB*NKPT*4)
#define OFF_PIX   (OFF_FEAS + BB*NFEAT*NKPT)

// Scratch
__device__ unsigned long long g_cand[BB*CAP];
__device__ unsigned char g_cmask[BB*HW];
__device__ int g_count[BB];
__device__ int g_done[BB];
__device__ int g_sel[BB*NKPT];

// 4-row rolling vertical 7-max from a 10-row register window.
__device__ __forceinline__ void vmax4(const float* __restrict__ colp,
                                      float out[4]) {
    float r[10];
    #pragma unroll
    for (int i = 0; i < 10; ++i) r[i] = colp[(i-3)*SPITCH];
    float t[9];
    #pragma unroll
    for (int i = 0; i < 9; ++i) t[i] = fmaxf(r[i], r[i+1]);
    float q[7];
    #pragma unroll
    for (int i = 0; i < 7; ++i) q[i] = fmaxf(t[i], t[i+2]);
    #pragma unroll
    for (int j = 0; j < 4; ++j) out[j] = fmaxf(q[j], q[j+3]);
}

// Fused 7x7 OR-dilation of mk bits -> sup bits
template<int R0, int NR>
__device__ __forceinline__ void p34(const unsigned int* __restrict__ mkw,
                                    unsigned int* __restrict__ spw, int tid) {
    for (int t = tid; t < NR*3; t += NMS_THREADS) {
        int row = R0 + t / 3, w = t % 3 + 1;
        unsigned a = 0, c = 0, d = 0;
        #pragma unroll
        for (int k = -3; k <= 3; ++k) {
            const unsigned int* mr = mkw + (row+k)*WPR;
            a |= mr[w-1]; c |= mr[w]; d |= mr[w+1];
        }
        unsigned res = c;
        res |= __funnelshift_l(a, c, 1) | __funnelshift_r(c, d, 1);
        res |= __funnelshift_l(a, c, 2) | __funnelshift_r(c, d, 2);
        res |= __funnelshift_l(a, c, 3) | __funnelshift_r(c, d, 3);
        spw[row*WPR + w] = res;
    }
}

// quad h-pool of suppressed scores
template<int R0, int NR, int Q0, int NQt>
__device__ __forceinline__ void p5_quads(const float* __restrict__ sc,
                                         float* __restrict__ tp,
                                         const unsigned int* __restrict__ spw,
                                         int tid) {
    for (int t = tid; t < NR*NQt; t += NMS_THREADS) {
        int ly = R0 + t / NQt;
        int x  = (Q0 + t % NQt) << 2;
        const float* row = sc + ly*SPITCH;
        const unsigned int* srG = spw + (ly+GR)*WPR;  // word0 = bits -32..-1
        int Bp = x + 29;                              // (x-3) + 32
        unsigned w0 = srG[Bp >> 5];
        unsigned w1 = srG[(Bp >> 5) + 1];
        unsigned win = __funnelshift_r(w0, w1, Bp);
        float4 a = *(const float4*)(row + x - 4);
        float4 c = *(const float4*)(row + x);
        float4 e = *(const float4*)(row + x + 4);
        float s0 = (win & 1u)    ? 0.f : a.y;
        float s1 = (win & 2u)    ? 0.f : a.z;
        float s2 = (win & 4u)    ? 0.f : a.w;
        float s3 = (win & 8u)    ? 0.f : c.x;
        float s4 = (win & 16u)   ? 0.f : c.y;
        float s5 = (win & 32u)   ? 0.f : c.z;
        float s6 = (win & 64u)   ? 0.f : c.w;
        float s7 = (win & 128u)  ? 0.f : e.x;
        float s8 = (win & 256u)  ? 0.f : e.y;
        float s9 = (win & 512u)  ? 0.f : e.z;
        float mc = fmaxf(fmaxf(s3, s4), fmaxf(s5, s6));
        float m0 = fmaxf(fmaxf(mc, s0), fmaxf(s1, s2));
        float m1 = fmaxf(fmaxf(mc, s7), fmaxf(s1, s2));
        float m2 = fmaxf(fmaxf(mc, s2), fmaxf(s7, s8));
        float m3 = fmaxf(fmaxf(mc, s7), fmaxf(s8, s9));
        *(float4*)(tp + ly*SPITCH + x) = make_float4(m0, m1, m2, m3);
    }
}

// warp-aggregated histogram add (convergence-safe)
__device__ __forceinline__ void hist_add(unsigned int* h, unsigned bin,
                                         bool valid) {
    unsigned vm = __ballot_sync(0xffffffffu, valid);
    if (valid) {
        unsigned peers = __match_any_sync(vm, bin);
        int lane = threadIdx.x & 31;
        if (lane == __ffs(peers) - 1)
            atomicAdd(&h[bin], (unsigned)__popc(peers));
    }
}

// Inclusive suffix scan (chunk granularity) across 1024 threads; 2 barriers.
__device__ __forceinline__ unsigned suffix_scan(unsigned chunk,
                                                unsigned* wtot, int tid) {
    int lane = tid & 31, wd = tid >> 5;
    unsigned v = chunk;
    #pragma unroll
    for (int off = 1; off < 32; off <<= 1) {
        unsigned o = __shfl_down_sync(0xffffffffu, v, off);
        if (lane + off < 32) v += o;
    }
    if (lane == 0) wtot[wd] = v;
    __syncthreads();
    if (wd == 0) {
        unsigned t = wtot[lane];
        unsigned s = t;
        #pragma unroll
        for (int off = 1; off < 32; off <<= 1) {
            unsigned o = __shfl_down_sync(0xffffffffu, s, off);
            if (lane + off < 32) s += o;
        }
        wtot[lane] = s - t;
    }
    __syncthreads();
    return v + wtot[wd];
}

// ---------------------------------------------------------------------------
// Selection for batch b (runs inside the LAST k_nms block of that batch).
// Two-level 12-bit radix threshold, compact survivors, exact rank in smem.
// Scratch: h (16KB) + sk (24KB) carved from dynamic smem (sbuf/tbuf region).
// ---------------------------------------------------------------------------
__device__ void do_select(int b, unsigned char* smraw) {
    unsigned int* h = (unsigned int*)smraw;                        // 16384 B
    unsigned long long* sk = (unsigned long long*)(smraw + 16384); // 24576 B
    __shared__ unsigned int wtot[32];
    __shared__ int sBin;
    __shared__ unsigned int sAbove;
    __shared__ unsigned long long sT;
    __shared__ int scnt;
    __shared__ int sn;

    const int tid = threadIdx.x;
    if (tid == 0) {
        sn = min(g_count[b], CAP);
        scnt = 0;
        sT = 0ULL;
    }
    __syncthreads();
    const int n = sn;
    const unsigned int target = (unsigned int)min(n, NKPT);
    const unsigned long long* base = g_cand + (size_t)b*CAP;

    if (target > 0) {
        const int nR = (n + 1023) & ~1023;

        // ---- level 1: bins = key bits [63:52] ----
        for (int i = tid; i < 4096; i += 1024) h[i] = 0;
        __syncthreads();
        for (int i = tid; i < nR; i += 1024) {
            bool valid = i < n;
            unsigned bin = valid ? (unsigned)(base[i] >> 52) : 0u;
            hist_add(h, bin, valid);
        }
        __syncthreads();
        unsigned h0 = h[4*tid], h1 = h[4*tid+1],
                 h2 = h[4*tid+2], h3 = h[4*tid+3];
        unsigned chunk = h0 + h1 + h2 + h3;
        unsigned S = suffix_scan(chunk, wtot, tid);
        {
            unsigned s4 = S - chunk;
            unsigned s3 = h3 + s4, s2 = h2 + s3, s1 = h1 + s2, s0 = h0 + s1;
            unsigned sf[5] = {s0, s1, s2, s3, s4};
            #pragma unroll
            for (int i = 0; i < 4; ++i)
                if (sf[i] >= target && sf[i+1] < target) {
                    sBin = 4*tid + i; sAbove = sf[i+1];
                }
        }
        __syncthreads();
        const unsigned long long B1 = (unsigned long long)sBin;
        const unsigned int rem = target - sAbove;   // >= 1

        // ---- level 2: bins = key bits [51:40], restricted to level-1 bin ----
        for (int i = tid; i < 4096; i += 1024) h[i] = 0;
        __syncthreads();
        for (int i = tid; i < nR; i += 1024) {
            bool valid = false;
            unsigned bin = 0;
            if (i < n) {
                unsigned long long key = base[i];
                if ((key >> 52) == B1) {
                    valid = true;
                    bin = (unsigned)(key >> 40) & 0xFFFu;
                }
            }
            hist_add(h, bin, valid);
        }
        __syncthreads();
        h0 = h[4*tid]; h1 = h[4*tid+1]; h2 = h[4*tid+2]; h3 = h[4*tid+3];
        chunk = h0 + h1 + h2 + h3;
        S = suffix_scan(chunk, wtot, tid);
        {
            unsigned s4 = S - chunk;
            unsigned s3 = h3 + s4, s2 = h2 + s3, s1 = h1 + s2, s0 = h0 + s1;
            unsigned sf[5] = {s0, s1, s2, s3, s4};
            #pragma unroll
            for (int i = 0; i < 4; ++i)
                if (sf[i] >= rem && sf[i+1] < rem)
                    sT = (B1 << 52) | ((unsigned long long)(4*tid + i) << 40);
        }
        __syncthreads();

        // ---- compact survivors, rank in smem ----
        const unsigned long long T = sT;
        for (int i = tid; i < n; i += 1024) {
            unsigned long long key = base[i];
            if (key >= T) {
                int p = atomicAdd(&scnt, 1);
                if (p < SURVCAP) sk[p] = key;
            }
        }
        __syncthreads();
        int m = scnt;

        if (m <= SURVCAP) {
            for (int i = tid; i < m; i += 1024) {
                unsigned long long key = sk[i];
                int r = 0;
                for (int j = 0; j < m; ++j) r += (sk[j] > key) ? 1 : 0;
                if (r < NKPT)
                    g_sel[b*NKPT + r] = HW - 1 - (int)(key & 0xffffffffu);
            }
        } else {
            // cold: exact rank via global scans, warp per survivor
            int lane = tid & 31, w = tid >> 5;
            for (int i = w; i < n; i += 32) {
                unsigned long long key = base[i];
                if (key < T) continue;
                int r = 0;
                for (int j = lane; j < n; j += 32)
                    r += (base[j] > key) ? 1 : 0;
                #pragma unroll
                for (int off = 16; off; off >>= 1)
                    r += __shfl_down_sync(0xffffffffu, r, off);
                if (lane == 0 && r < NKPT)
                    g_sel[b*NKPT + r] = HW - 1 - (int)(key & 0xffffffffu);
            }
        }
    }

    // cold: fewer than NKPT candidates -> ascending non-candidate indices
    if (n < NKPT) {
        __syncthreads();
        if (tid == 0) {
            int slot = n;
            for (int p = 0; p < HW && slot < NKPT; ++p)
                if (!g_cmask[b*HW + p]) g_sel[b*NKPT + (slot++)] = p;
        }
    }
}

// ---------------------------------------------------------------------------
// Fused NMS + last-block selection. One block per 64x64 tile, 1024 threads,
// 2 blocks/SM. The last-finishing block of each batch runs do_select.
// ---------------------------------------------------------------------------
__global__ __launch_bounds__(NMS_THREADS, 2)
void k_nms(const float* __restrict__ bev,
           const float* __restrict__ raw,
           float* __restrict__ out) {
    extern __shared__ unsigned char smraw[];
    float* sbuf = (float*)smraw;
    float* tbuf = sbuf + BUF;
    unsigned int* mkw = (unsigned int*)(tbuf + BUF);  // max_mask bits
    unsigned int* spw = mkw + RROWS*WPR;              // supp (7x7 dil) bits
    float* sc = sbuf + GR*SPITCH + GC;
    float* tp = tbuf + GR*SPITCH + GC;

    const int tid  = threadIdx.x;
    const int wid  = tid >> 5;
    const int lane = tid & 31;
    const int b    = blockIdx.z;
    const int gy0  = blockIdx.y * TILE - HALO;
    const int bx64 = blockIdx.x * TILE;
    const float* g2 = bev + (b*7 + 2)*HW;
    const float* rw = raw + b*HW;

    // bit arrays init (guard words/rows stay zero forever)
    for (int i = tid; i < RROWS*WPR; i += NMS_THREADS) {
        mkw[i] = 0; spw[i] = 0;
    }

    // load pass: warp per row; lanes 0-23 = aligned float4 quads (cols 3..98),
    // lanes 24-31 = edge columns {0,1,2,99..103}; -inf outside image.
    for (int r = wid; r < RROWS; r += NMS_NW) {
        int gy = gy0 + (r - GR);
        bool rowin = (unsigned)gy < HH;
        const float* rwr = rw + gy*WW;
        const float* g2r = g2 + gy*WW;
        if (lane < 24) {
            int col = 3 + (lane << 2);
            int gx = bx64 + col - 19;
            float4 v = make_float4(-CUDART_INF_F, -CUDART_INF_F,
                                   -CUDART_INF_F, -CUDART_INF_F);
            if (rowin) {
                if (gx >= 0 && gx + 3 < WW) {
                    float4 r4 = *(const float4*)(rwr + gx);
                    float4 g4 = *(const float4*)(g2r + gx);
                    v.x = r4.x * (g4.x > 0.f ? 1.f : 0.f);
                    v.y = r4.y * (g4.y > 0.f ? 1.f : 0.f);
                    v.z = r4.z * (g4.z > 0.f ? 1.f : 0.f);
                    v.w = r4.w * (g4.w > 0.f ? 1.f : 0.f);
                } else {
                    float* vp = &v.x;
                    #pragma unroll
                    for (int i = 0; i < 4; ++i) {
                        int gxi = gx + i;
                        if ((unsigned)gxi < WW)
                            vp[i] = rwr[gxi] * (g2r[gxi] > 0.f ? 1.f : 0.f);
                    }
                }
            }
            float* dst = sbuf + r*SPITCH + col;
            dst[0] = v.x; dst[1] = v.y; dst[2] = v.z; dst[3] = v.w;
        } else {
            int i8 = lane - 24;
            int col = (i8 < 3) ? i8 : 96 + i8;   // 0,1,2, 99..103
            int gx = bx64 + col - 19;
            float v = -CUDART_INF_F;
            if (rowin && (unsigned)gx < WW)
                v = rwr[gx] * (g2r[gx] > 0.f ? 1.f : 0.f);
            sbuf[r*SPITCH + col] = v;
        }
    }
    __syncthreads();

    // P1: h 7-max sc -> tp, quads, all 94 rows
    for (int t = tid; t < 94*24; t += NMS_THREADS) {
        int ly = t / 24;
        int x  = (t % 24) << 2;
        const float* row = sc + ly*SPITCH;
        float4 a = *(const float4*)(row + x - 4);
        float4 c = *(const float4*)(row + x);
        float4 e = *(const float4*)(row + x + 4);
        float mc = fmaxf(fmaxf(c.x, c.y), fmaxf(c.z, c.w));
        float m0 = fmaxf(fmaxf(mc, a.y), fmaxf(a.z, a.w));
        float m1 = fmaxf(fmaxf(mc, e.x), fmaxf(a.z, a.w));
        float m2 = fmaxf(fmaxf(mc, a.w), fmaxf(e.x, e.y));
        float m3 = fmaxf(fmaxf(mc, e.x), fmaxf(e.y, e.z));
        *(float4*)(tp + ly*SPITCH + x) = make_float4(m0, m1, m2, m3);
    }
    __syncthreads();
    // P2: v 7-max of tp over rows [3,91) in 4-row strips;
    // mk bit = (max == sc) & in-image.
    for (int t = wid; t < 66; t += NMS_NW) {
        int s = t / 3, g = t % 3;
        int r0 = 3 + s*4;
        int lx = g*32 + lane;
        bool inb = lx < LDIM;
        float vm[4];
        vmax4(tp + r0*SPITCH + lx, vm);
        #pragma unroll
        for (int j = 0; j < 4; ++j) {
            bool pred = false;
            if (inb) {
                float sv = sc[(r0+j)*SPITCH + lx];
                pred = (vm[j] == sv && sv >= 0.f);
            }
            unsigned bal = __ballot_sync(0xffffffffu, pred);
            if (lane == 0) mkw[(r0+j+GR)*WPR + 1 + g] = bal;
        }
    }
    __syncthreads();

    // ---- iteration 0 ----
    p34<9, 82>(mkw, spw, tid);
    __syncthreads();
    p5_quads<6, 82, 0, 24>(sc, tp, spw, tid);
    __syncthreads();
    // P6 it0: rows [9,85) in 4-row strips
    for (int t = wid; t < 57; t += NMS_NW) {
        int s = t / 3, g = t % 3;
        int r0 = 9 + s*4;
        int lx = g*32 + lane;
        bool inb = lx < LDIM;
        float vm[4];
        vmax4(tp + r0*SPITCH + lx, vm);
        #pragma unroll
        for (int j = 0; j < 4; ++j) {
            bool cond = false;
            if (inb) {
                float sv = sc[(r0+j)*SPITCH + lx];
                unsigned supb = (spw[(r0+j+GR)*WPR + 1 + g] >> lane) & 1u;
                cond = (!supb && sv >= 0.f && vm[j] == sv);
            }
            unsigned bal = __ballot_sync(0xffffffffu, cond);
            if (lane == 0 && bal) mkw[(r0+j+GR)*WPR + 1 + g] |= bal;
        }
    }
    __syncthreads();

    // ---- iteration 1 ----
    p34<15, 70>(mkw, spw, tid);
    __syncthreads();
    p5_quads<12, 70, 3, 18>(sc, tp, spw, tid);
    __syncthreads();
    // P6 it1 (emit): interior only; 16 strips x 2 groups = 32 warp tasks;
    // ONE aggregated atomic per warp (4 rows).
    {
        int s = wid >> 1, g = wid & 1;
        int r0 = HALO + s*4;
        int lx = HALO + g*32 + lane;
        float vm[4];
        vmax4(tp + r0*SPITCH + lx, vm);
        unsigned cb[4];
        float svv[4];
        #pragma unroll
        for (int j = 0; j < 4; ++j) {
            int ly = r0 + j;
            float sv = sc[ly*SPITCH + lx];
            unsigned supb = (spw[(ly+GR)*WPR + 1 + (lx >> 5)]
                             >> (lx & 31)) & 1u;
            bool cond = (!supb && sv >= 0.f && vm[j] == sv);
            bool fm = cond || ((mkw[(ly+GR)*WPR + 1 + (lx >> 5)]
                                >> (lx & 31)) & 1u);
            int gg = (blockIdx.y*TILE + ly - HALO)*WW
                     + bx64 + lx - HALO;
            out[OFF_SCORE + b*HW + gg] = sv;
            bool c = fm && (sv > 0.f);
            g_cmask[b*HW + gg] = c ? 1 : 0;
            cb[j] = __ballot_sync(0xffffffffu, c);
            svv[j] = sv;
        }
        int total = __popc(cb[0]) + __popc(cb[1])
                  + __popc(cb[2]) + __popc(cb[3]);
        int basep = 0;
        if (lane == 0 && total) basep = atomicAdd(&g_count[b], total);
        basep = __shfl_sync(0xffffffffu, basep, 0);
        #pragma unroll
        for (int j = 0; j < 4; ++j) {
            if ((cb[j] >> lane) & 1u) {
                int pos = basep + __popc(cb[j] & ((1u << lane) - 1u));
                if (pos < CAP) {
                    int gg = (blockIdx.y*TILE + r0 + j - HALO)*WW
                             + bx64 + lx - HALO;
                    unsigned long long key =
                        ((unsigned long long)__float_as_uint(svv[j]) << 32)
                        | (unsigned int)(HW - 1 - gg);
                    g_cand[b*CAP + pos] = key;
                }
            }
            basep += __popc(cb[j]);
        }
    }

    // ---- last-block election: the 64th finishing block of batch b selects.
    __shared__ int sLast;
    __threadfence();            // make this thread's global writes visible
    __syncthreads();            // all threads' writes fenced before ticket
    if (tid == 0) {
        int d = atomicAdd(&g_done[b], 1);
        sLast = (d == 63) ? 1 : 0;
    }
    __syncthreads();
    if (sLast) do_select(b, smraw);
}

// ---------------------------------------------------------------------------
// Gather: each thread handles 8 channels of one keypoint; kpts/pixels from
// groups 0..BB-1; resets g_count/g_done for next replay (after all readers).
// ---------------------------------------------------------------------------
__global__ __launch_bounds__(256)
void k_gather(const float* __restrict__ bev,
              const float* __restrict__ feat,
              float* __restrict__ out) {
    int t = blockIdx.x * blockDim.x + threadIdx.x;   // 32768 threads
    if (t < BB) { g_count[t] = 0; g_done[t] = 0; }
    int k   = t & (NKPT-1);
    int grp = t >> 9;            // (b, cq): 4 * 16
    int b   = grp >> 4;
    int cq  = grp & 15;
    int idx = g_sel[b*NKPT + k];

    if (grp < BB) {
        int bk = grp;
        int idk = g_sel[bk*NKPT + k];
        int u = idk / WW, v = idk - u*WW;
        float4 kv = make_float4(bev[(bk*7 + 3)*HW + idk],
                                bev[(bk*7 + 4)*HW + idk], 0.f, 1.f);
        ((float4*)(out + OFF_KPTS))[bk*NKPT + k] = kv;
        ((float2*)(out + OFF_PIX))[bk*NKPT + k] =
            make_float2((float)u, (float)v);
    }

    const float* fb = feat + ((size_t)(b*NFEAT + cq*8))*HW + idx;
    float v0 = fb[0*HW];
    float v1 = fb[1*HW];
    float v2 = fb[2*HW];
    float v3 = fb[3*HW];
    float v4 = fb[4*HW];
    float v5 = fb[5*HW];
    float v6 = fb[6*HW];
    float v7 = fb[7*HW];
    float* ob = out + OFF_FEAS + (size_t)(b*NFEAT + cq*8)*NKPT + k;
    ob[0*NKPT] = v0;
    ob[1*NKPT] = v1;
    ob[2*NKPT] = v2;
    ob[3*NKPT] = v3;
    ob[4*NKPT] = v4;
    ob[5*NKPT] = v5;
    ob[6*NKPT] = v6;
    ob[7*NKPT] = v7;
}

extern "C" void kernel_launch(void* const* d_in, const int* in_sizes, int n_in,
                              void* d_out, int out_size) {
    const float* bev  = (const float*)d_in[0];
    const float* raw  = (const float*)d_in[1];
    const float* feat = (const float*)d_in[2];
    float* out = (float*)d_out;

    static bool attr_set = false;
    if (!attr_set) {
        cudaFuncSetAttribute(k_nms, cudaFuncAttributeMaxDynamicSharedMemorySize,
                             NMS_SMEM);
        attr_set = true;
    }

    dim3 ngrid(WW/TILE, HH/TILE, BB);   // 8 x 8 x 4
    k_nms<<<ngrid, NMS_THREADS, NMS_SMEM>>>(bev, raw, out);
    k_gather<<<128, 256>>>(bev, feat, out);
}